// round 10
// baseline (speedup 1.0000x reference)
#include <cuda_runtime.h>
#include <cuda_bf16.h>
#include <cstdint>

#define N_NODES 50000
#define N_GRAPHS 1024
#define MAXC 256

// ---------------- static scratch (no allocation allowed) ----------------
__device__ float d_h  [N_NODES * MAXC];
__device__ float d_agg[N_NODES * MAXC];
__device__ float d_res[N_NODES * MAXC];
__device__ float d_xa [N_NODES * MAXC];
__device__ float d_xb [N_NODES * MAXC];
__device__ float d_deg [N_NODES];
__device__ float d_dinv[N_NODES];
__device__ float d_fp  [N_GRAPHS * MAXC];
__device__ float d_fg  [N_GRAPHS * MAXC];
__device__ float d_sums[N_GRAPHS * MAXC];
__device__ float d_cnt [N_GRAPHS];

// ---------------- helpers ----------------
__device__ __forceinline__ void tf32_split(float a, float& hi, float& lo) {
    uint32_t hb;
    asm("cvt.rna.tf32.f32 %0, %1;" : "=r"(hb) : "f"(a));
    hi = __uint_as_float(hb);
    lo = a - hi;
}
__device__ __forceinline__ void mma_tf32(float* d, const uint32_t* a, const uint32_t* b) {
    asm volatile(
        "mma.sync.aligned.m16n8k8.row.col.f32.tf32.tf32.f32 "
        "{%0,%1,%2,%3}, {%4,%5,%6,%7}, {%8,%9}, {%0,%1,%2,%3};"
        : "+f"(d[0]), "+f"(d[1]), "+f"(d[2]), "+f"(d[3])
        : "r"(a[0]), "r"(a[1]), "r"(a[2]), "r"(a[3]), "r"(b[0]), "r"(b[1]));
}

// ---------------- init / degree ----------------
__global__ void zero_kernel() {
    int total = N_NODES + N_GRAPHS * MAXC + N_GRAPHS;
    for (int i = blockIdx.x * blockDim.x + threadIdx.x; i < total;
         i += gridDim.x * blockDim.x) {
        if (i < N_NODES) d_deg[i] = 0.0f;
        else if (i < N_NODES + N_GRAPHS * MAXC) d_sums[i - N_NODES] = 0.0f;
        else d_cnt[i - N_NODES - N_GRAPHS * MAXC] = 0.0f;
    }
}
__global__ void deg_kernel(const int* __restrict__ ei, int E) {
    int e = blockIdx.x * blockDim.x + threadIdx.x;
    if (e < E) {
        unsigned d = (unsigned)ei[E + e];
        if (d < N_NODES) atomicAdd(&d_deg[d], 1.0f);
    }
}
__global__ void dinv_kernel() {
    int i = blockIdx.x * blockDim.x + threadIdx.x;
    if (i < N_NODES) d_dinv[i] = rsqrtf(d_deg[i] + 1.0f);
}

// ================= split-tf32 mma.sync GEMM =================
// C[M,N] = A[M,K] @ W[K,N], fp32-accurate (3-product tf32 split).
// CTA tile 128x128, BK=32, 8 warps of 64x32. Requires K%32==0, N%128==0.
// Epilogue: v = acc*rowscale[row] + bias[col]; relu; store C (+C2).
#define TSTR 36                      // smem row stride (floats): 4*grp+tg conflict-free
#define TG_TILE (128 * TSTR)         // floats per tile buffer
#define TG_SMEM (4 * TG_TILE * 4)    // bytes: Ah, Al, Bh, Bl

__global__ __launch_bounds__(256)
void tgemm_kernel(const float* __restrict__ A, const float* __restrict__ W,
                  const float* __restrict__ bias, const float* __restrict__ rowscale,
                  float* __restrict__ C, float* __restrict__ C2,
                  int M, int N, int K, int do_relu)
{
    extern __shared__ float sm[];
    float* Ah = sm;
    float* Al = Ah + TG_TILE;
    float* Bh = Al + TG_TILE;
    float* Bl = Bh + TG_TILE;

    int tid  = threadIdx.x;
    int lane = tid & 31;
    int warp = tid >> 5;
    int grp  = lane >> 2;     // 0..7
    int tg   = lane & 3;      // 0..3
    int wm   = warp & 1;      // m-block (2 x 64)
    int wn   = warp >> 1;     // n-block (4 x 32)
    int row0 = blockIdx.y * 128;
    int col0 = blockIdx.x * 128;

    float acc[4][4][4];
    #pragma unroll
    for (int i = 0; i < 4; i++)
        #pragma unroll
        for (int j = 0; j < 4; j++)
            #pragma unroll
            for (int k = 0; k < 4; k++) acc[i][j][k] = 0.0f;

    const int nchunks = K >> 5;
    float4 ra[4], rb[4];

    // ---- stage chunk kt from gmem into registers
    auto gload = [&](int kt) {
        int k0 = kt << 5;
        #pragma unroll
        for (int l = 0; l < 4; l++) {
            int idx = tid + l * 256;          // 0..1023 float4 units
            int ar  = idx >> 3;               // 0..127
            int ac  = idx & 7;                // 0..7
            int gr  = row0 + ar;
            ra[l] = (gr < M) ? *(const float4*)&A[(size_t)gr * K + k0 + ac * 4]
                             : make_float4(0.f, 0.f, 0.f, 0.f);
            int kk = idx >> 5;                // 0..31
            int n4 = idx & 31;                // 0..31
            rb[l] = *(const float4*)&W[(size_t)(k0 + kk) * N + col0 + n4 * 4];
        }
    };
    // ---- split + store staged chunk into smem
    auto sstore = [&]() {
        #pragma unroll
        for (int l = 0; l < 4; l++) {
            int idx = tid + l * 256;
            int ar  = idx >> 3;
            int ac  = idx & 7;
            float4 h, lo;
            tf32_split(ra[l].x, h.x, lo.x);
            tf32_split(ra[l].y, h.y, lo.y);
            tf32_split(ra[l].z, h.z, lo.z);
            tf32_split(ra[l].w, h.w, lo.w);
            *(float4*)&Ah[ar * TSTR + ac * 4] = h;
            *(float4*)&Al[ar * TSTR + ac * 4] = lo;
            int kk = idx >> 5;
            int n4 = idx & 31;
            float hv[4], lv[4];
            tf32_split(rb[l].x, hv[0], lv[0]);
            tf32_split(rb[l].y, hv[1], lv[1]);
            tf32_split(rb[l].z, hv[2], lv[2]);
            tf32_split(rb[l].w, hv[3], lv[3]);
            #pragma unroll
            for (int j = 0; j < 4; j++) {
                int n = n4 * 4 + j;
                Bh[n * TSTR + kk] = hv[j];
                Bl[n * TSTR + kk] = lv[j];
            }
        }
    };

    gload(0);
    sstore();
    __syncthreads();

    for (int kt = 0; kt < nchunks; kt++) {
        if (kt + 1 < nchunks) gload(kt + 1);

        #pragma unroll
        for (int ks = 0; ks < 4; ks++) {
            int Kb = ks * 8;
            uint32_t afh[4][4], afl[4][4], bfh[4][2], bfl[4][2];
            #pragma unroll
            for (int mt = 0; mt < 4; mt++) {
                int r0 = (wm * 64 + mt * 16 + grp) * TSTR + Kb + tg;
                int r1 = r0 + 8 * TSTR;
                afh[mt][0] = __float_as_uint(Ah[r0]);
                afh[mt][1] = __float_as_uint(Ah[r1]);
                afh[mt][2] = __float_as_uint(Ah[r0 + 4]);
                afh[mt][3] = __float_as_uint(Ah[r1 + 4]);
                afl[mt][0] = __float_as_uint(Al[r0]);
                afl[mt][1] = __float_as_uint(Al[r1]);
                afl[mt][2] = __float_as_uint(Al[r0 + 4]);
                afl[mt][3] = __float_as_uint(Al[r1 + 4]);
            }
            #pragma unroll
            for (int nt = 0; nt < 4; nt++) {
                int nb = (wn * 32 + nt * 8 + grp) * TSTR + Kb + tg;
                bfh[nt][0] = __float_as_uint(Bh[nb]);
                bfh[nt][1] = __float_as_uint(Bh[nb + 4]);
                bfl[nt][0] = __float_as_uint(Bl[nb]);
                bfl[nt][1] = __float_as_uint(Bl[nb + 4]);
            }
            #pragma unroll
            for (int mt = 0; mt < 4; mt++)
                #pragma unroll
                for (int nt = 0; nt < 4; nt++) {
                    mma_tf32(acc[mt][nt], afh[mt], bfh[nt]);
                    mma_tf32(acc[mt][nt], afh[mt], bfl[nt]);
                    mma_tf32(acc[mt][nt], afl[mt], bfh[nt]);
                }
        }

        if (kt + 1 < nchunks) {
            __syncthreads();
            sstore();
            __syncthreads();
        }
    }

    // ---- epilogue: D fragment rows grp/grp+8, cols 2*tg, 2*tg+1
    #pragma unroll
    for (int mt = 0; mt < 4; mt++) {
        int r0 = row0 + wm * 64 + mt * 16 + grp;
        int r1 = r0 + 8;
        float rs0 = (rowscale && r0 < M) ? rowscale[r0] : 1.0f;
        float rs1 = (rowscale && r1 < M) ? rowscale[r1] : 1.0f;
        #pragma unroll
        for (int nt = 0; nt < 4; nt++) {
            int c = col0 + wn * 32 + nt * 8 + 2 * tg;
            float b0 = bias ? bias[c] : 0.0f;
            float b1 = bias ? bias[c + 1] : 0.0f;
            float v0 = acc[mt][nt][0] * rs0 + b0;
            float v1 = acc[mt][nt][1] * rs0 + b1;
            float v2 = acc[mt][nt][2] * rs1 + b0;
            float v3 = acc[mt][nt][3] * rs1 + b1;
            if (do_relu) {
                v0 = fmaxf(v0, 0.f); v1 = fmaxf(v1, 0.f);
                v2 = fmaxf(v2, 0.f); v3 = fmaxf(v3, 0.f);
            }
            if (r0 < M) {
                float2 p = make_float2(v0, v1);
                *(float2*)&C[(size_t)r0 * N + c] = p;
                if (C2) *(float2*)&C2[(size_t)r0 * N + c] = p;
            }
            if (r1 < M) {
                float2 p = make_float2(v2, v3);
                *(float2*)&C[(size_t)r1 * N + c] = p;
                if (C2) *(float2*)&C2[(size_t)r1 * N + c] = p;
            }
        }
    }
}

// ---------------- SIMT fgemm (fp branch: M=1024, K=2048, N=256) ------------
__global__ __launch_bounds__(256, 1)
void fgemm_kernel(const float* __restrict__ A, const float* __restrict__ B,
                  const float* __restrict__ bias, const float* __restrict__ rowscale,
                  float* __restrict__ C, float* __restrict__ C2,
                  int M, int N, int K, int do_relu)
{
    const int BM = 128, BN = 128, BK = 16;
    __shared__ float As[2][BK][BM + 4];
    __shared__ float Bs[2][BK][BN];
    int tid = threadIdx.x;
    int tx  = tid & 15;
    int ty  = tid >> 4;
    int row0 = blockIdx.y * BM;
    int col0 = blockIdx.x * BN;
    float acc[8][8];
    #pragma unroll
    for (int i = 0; i < 8; i++)
        #pragma unroll
        for (int j = 0; j < 8; j++) acc[i][j] = 0.0f;
    const int ntiles = K / BK;
    float4 pa[2], pb[2];
    auto gload = [&](int kt) {
        int k0 = kt * BK;
        #pragma unroll
        for (int l = 0; l < 2; l++) {
            int idx = tid + l * 256;
            int ar  = idx >> 2;
            int ac4 = idx & 3;
            int gr  = row0 + ar;
            pa[l] = (gr < M) ? *(const float4*)&A[(size_t)gr * K + k0 + ac4 * 4]
                             : make_float4(0.f, 0.f, 0.f, 0.f);
            int br  = idx >> 5;
            int bc4 = idx & 31;
            pb[l] = *(const float4*)&B[(size_t)(k0 + br) * N + col0 + bc4 * 4];
        }
    };
    auto sstore = [&](int buf) {
        #pragma unroll
        for (int l = 0; l < 2; l++) {
            int idx = tid + l * 256;
            int ar  = idx >> 2;
            int ac4 = idx & 3;
            As[buf][ac4 * 4 + 0][ar] = pa[l].x;
            As[buf][ac4 * 4 + 1][ar] = pa[l].y;
            As[buf][ac4 * 4 + 2][ar] = pa[l].z;
            As[buf][ac4 * 4 + 3][ar] = pa[l].w;
            int br  = idx >> 5;
            int bc4 = idx & 31;
            *(float4*)&Bs[buf][br][bc4 * 4] = pb[l];
        }
    };
    gload(0); sstore(0); __syncthreads();
    for (int kt = 0; kt < ntiles; kt++) {
        int cur = kt & 1;
        if (kt + 1 < ntiles) gload(kt + 1);
        #pragma unroll
        for (int kk = 0; kk < BK; kk++) {
            float a[8], b[8];
            *(float4*)&a[0] = *(const float4*)&As[cur][kk][ty * 8];
            *(float4*)&a[4] = *(const float4*)&As[cur][kk][ty * 8 + 4];
            *(float4*)&b[0] = *(const float4*)&Bs[cur][kk][tx * 8];
            *(float4*)&b[4] = *(const float4*)&Bs[cur][kk][tx * 8 + 4];
            #pragma unroll
            for (int i = 0; i < 8; i++)
                #pragma unroll
                for (int j = 0; j < 8; j++)
                    acc[i][j] = fmaf(a[i], b[j], acc[i][j]);
        }
        if (kt + 1 < ntiles) { sstore(cur ^ 1); __syncthreads(); }
    }
    float bvals[8];
    if (bias) {
        *(float4*)&bvals[0] = *(const float4*)&bias[col0 + tx * 8];
        *(float4*)&bvals[4] = *(const float4*)&bias[col0 + tx * 8 + 4];
    } else {
        #pragma unroll
        for (int j = 0; j < 8; j++) bvals[j] = 0.0f;
    }
    #pragma unroll
    for (int i = 0; i < 8; i++) {
        int gr = row0 + ty * 8 + i;
        if (gr >= M) continue;
        float rs = rowscale ? rowscale[gr] : 1.0f;
        float v[8];
        #pragma unroll
        for (int j = 0; j < 8; j++) {
            float t = acc[i][j] * rs + bvals[j];
            v[j] = do_relu ? fmaxf(t, 0.0f) : t;
        }
        size_t base = (size_t)gr * N + col0 + tx * 8;
        *(float4*)&C[base]     = *(float4*)&v[0];
        *(float4*)&C[base + 4] = *(float4*)&v[4];
        if (C2) {
            *(float4*)&C2[base]     = *(float4*)&v[0];
            *(float4*)&C2[base + 4] = *(float4*)&v[4];
        }
    }
}

// ---------------- generic (slow) SGEMM for irregular shapes (K=167) --------
template<int BM, int BN, int BK>
__global__ __launch_bounds__(256)
void sgemm_kernel(const float* __restrict__ A, const float* __restrict__ W,
                  const float* __restrict__ bias, const float* __restrict__ rowscale,
                  float* __restrict__ C, float* __restrict__ C2,
                  int M, int N, int K, int do_relu)
{
    __shared__ float As[BM][BK + 1];
    __shared__ float Bs[BK][BN + 1];
    const int TM = 4, TN = 4;
    int tid = threadIdx.x;
    int tx  = tid % (BN / TN);
    int ty  = tid / (BN / TN);
    int row0 = blockIdx.y * BM;
    int col0 = blockIdx.x * BN;
    float acc[TM][TN];
    #pragma unroll
    for (int i = 0; i < TM; i++)
        #pragma unroll
        for (int j = 0; j < TN; j++) acc[i][j] = 0.0f;
    for (int k0 = 0; k0 < K; k0 += BK) {
        for (int i = tid; i < BM * BK; i += 256) {
            int r = i / BK, c = i % BK;
            int gr = row0 + r, gc = k0 + c;
            As[r][c] = (gr < M && gc < K) ? A[(size_t)gr * K + gc] : 0.0f;
        }
        for (int i = tid; i < BK * BN; i += 256) {
            int r = i / BN, c = i % BN;
            int gr = k0 + r, gc = col0 + c;
            Bs[r][c] = (gr < K && gc < N) ? W[(size_t)gr * N + gc] : 0.0f;
        }
        __syncthreads();
        #pragma unroll
        for (int kk = 0; kk < BK; kk++) {
            float a[TM], b[TN];
            #pragma unroll
            for (int i = 0; i < TM; i++) a[i] = As[ty * TM + i][kk];
            #pragma unroll
            for (int j = 0; j < TN; j++) b[j] = Bs[kk][tx * TN + j];
            #pragma unroll
            for (int i = 0; i < TM; i++)
                #pragma unroll
                for (int j = 0; j < TN; j++) acc[i][j] += a[i] * b[j];
        }
        __syncthreads();
    }
    #pragma unroll
    for (int i = 0; i < TM; i++) {
        int gr = row0 + ty * TM + i;
        if (gr >= M) continue;
        float rs = rowscale ? rowscale[gr] : 1.0f;
        #pragma unroll
        for (int j = 0; j < TN; j++) {
            int gc = col0 + tx * TN + j;
            if (gc >= N) continue;
            float v = acc[i][j] * rs;
            if (bias) v += bias[gc];
            if (do_relu) v = fmaxf(v, 0.0f);
            C[(size_t)gr * N + gc] = v;
            if (C2) C2[(size_t)gr * N + gc] = v;
        }
    }
}

// ---------------- edge scatter: agg[dst] += g[src] ----------------
__global__ void scatter_kernel(const int* __restrict__ ei, int E, int C) {
    int gw   = (blockIdx.x * blockDim.x + threadIdx.x) >> 5;
    int lane = threadIdx.x & 31;
    int nw   = (gridDim.x * blockDim.x) >> 5;
    for (int e = gw; e < E; e += nw) {
        unsigned s = (unsigned)ei[e];
        unsigned d = (unsigned)ei[E + e];
        if (s >= N_NODES || d >= N_NODES) continue;
        const float4* gs = (const float4*)(d_h + (size_t)s * C);
        float* ad = d_agg + (size_t)d * C;
        int c4 = C >> 2;
        for (int c = lane; c < c4; c += 32) {
            float4 v = gs[c];
            float* p = ad + 4 * c;
            asm volatile("red.global.add.v4.f32 [%0], {%1, %2, %3, %4};"
                         :: "l"(p), "f"(v.x), "f"(v.y), "f"(v.z), "f"(v.w)
                         : "memory");
        }
    }
}

// ---------------- combine: x_next = relu(dinv*agg + b (+ res)) ----------------
__global__ void combine_kernel(const float* __restrict__ bias,
                               const float* __restrict__ res,
                               float* __restrict__ out, int C) {
    size_t i = (size_t)blockIdx.x * blockDim.x + threadIdx.x;
    size_t total = (size_t)N_NODES * C;
    if (i >= total) return;
    int row = (int)(i / C);
    int col = (int)(i % C);
    float v = d_dinv[row] * d_agg[i] + bias[col];
    if (res) v += res[i];
    out[i] = fmaxf(v, 0.0f);
}

// ---------------- fused softmax-attention + mean-pool accumulate ----------------
__global__ void pool_kernel(const int* __restrict__ batch) {
    int node = (blockIdx.x * blockDim.x + threadIdx.x) >> 5;
    int lane = threadIdx.x & 31;
    if (node >= N_NODES) return;
    const float* srow = d_h  + (size_t)node * 256;
    const float* xrow = d_xa + (size_t)node * 256;
    float vals[8];
    float m = -3.0e38f;
    #pragma unroll
    for (int j = 0; j < 8; j++) { vals[j] = srow[lane + 32 * j]; m = fmaxf(m, vals[j]); }
    #pragma unroll
    for (int off = 16; off; off >>= 1) m = fmaxf(m, __shfl_xor_sync(0xffffffffu, m, off));
    float ssum = 0.0f;
    #pragma unroll
    for (int j = 0; j < 8; j++) { vals[j] = __expf(vals[j] - m); ssum += vals[j]; }
    #pragma unroll
    for (int off = 16; off; off >>= 1) ssum += __shfl_xor_sync(0xffffffffu, ssum, off);
    float inv = 1.0f / ssum;
    unsigned b = (unsigned)batch[node];
    if (b >= N_GRAPHS) return;
    float* orow = d_sums + (size_t)b * 256;
    #pragma unroll
    for (int j = 0; j < 8; j++) {
        atomicAdd(orow + lane + 32 * j, vals[j] * inv * xrow[lane + 32 * j]);
    }
    if (lane == 0) atomicAdd(&d_cnt[b], 1.0f);
}

// ---------------- final: out = (pooled + fp + fg) @ Wfc + bfc ----------------
__global__ void final_kernel(const float* __restrict__ Wfc,
                             const float* __restrict__ bfc,
                             float* __restrict__ out) {
    int b    = (blockIdx.x * blockDim.x + threadIdx.x) >> 5;
    int lane = threadIdx.x & 31;
    if (b >= N_GRAPHS) return;
    float invc = 1.0f / fmaxf(d_cnt[b], 1.0f);
    float acc = 0.0f;
    #pragma unroll
    for (int j = lane; j < 256; j += 32) {
        float v = d_sums[b * 256 + j] * invc + d_fp[b * 256 + j] + d_fg[b * 256 + j];
        acc += v * Wfc[j];
    }
    #pragma unroll
    for (int off = 16; off; off >>= 1) acc += __shfl_xor_sync(0xffffffffu, acc, off);
    if (lane == 0) out[b] = acc + bfc[0];
}

// ---------------- launch ----------------
extern "C" void kernel_launch(void* const* d_in, const int* in_sizes, int n_in,
                              void* d_out, int out_size) {
    const float* x     = (const float*)d_in[0];
    const int*   ei    = (const int*)d_in[1];
    const int*   batch = (const int*)d_in[2];
    const float* fpf = (const float*)d_in[3];
    const float* fgr = (const float*)d_in[4];
    const float* W1  = (const float*)d_in[5],  *b1  = (const float*)d_in[6];
    const float* W2  = (const float*)d_in[7],  *b2  = (const float*)d_in[8];
    const float* W3  = (const float*)d_in[9],  *b3  = (const float*)d_in[10];
    const float* Wr1 = (const float*)d_in[11], *br1 = (const float*)d_in[12];
    const float* Wr2 = (const float*)d_in[13], *br2 = (const float*)d_in[14];
    const float* Wfp = (const float*)d_in[15], *bfp = (const float*)d_in[16];
    const float* Wfg = (const float*)d_in[17], *bfg = (const float*)d_in[18];
    const float* attn_W = (const float*)d_in[19];
    const float* Wfc = (const float*)d_in[20], *bfc = (const float*)d_in[21];
    float* out = (float*)d_out;
    int E = in_sizes[1] / 2;

    float *ph, *pagg, *pres, *pxa, *pxb, *pdinv, *pfp, *pfg;
    cudaGetSymbolAddress((void**)&ph,   d_h);
    cudaGetSymbolAddress((void**)&pagg, d_agg);
    cudaGetSymbolAddress((void**)&pres, d_res);
    cudaGetSymbolAddress((void**)&pxa,  d_xa);
    cudaGetSymbolAddress((void**)&pxb,  d_xb);
    cudaGetSymbolAddress((void**)&pdinv, d_dinv);
    cudaGetSymbolAddress((void**)&pfp,  d_fp);
    cudaGetSymbolAddress((void**)&pfg,  d_fg);

    cudaFuncSetAttribute(tgemm_kernel,
                         cudaFuncAttributeMaxDynamicSharedMemorySize, TG_SMEM);

    const int T = 256;
    auto cdiv = [](int a, int b) { return (a + b - 1) / b; };

    zero_kernel<<<cdiv(N_NODES + N_GRAPHS * MAXC + N_GRAPHS, T), T>>>();
    deg_kernel<<<cdiv(E, T), T>>>(ei, E);
    dinv_kernel<<<cdiv(N_NODES, T), T>>>();

    dim3 tN128(1, cdiv(N_NODES, 128));
    dim3 tN256(2, cdiv(N_NODES, 128));
    dim3 gB256f(2, cdiv(N_GRAPHS, 128));
    dim3 gB256s(256 / 64, cdiv(N_GRAPHS, 64));
    int scatterBlocks = cdiv(E, 8);

    // ---- Layer 1
    tgemm_kernel<<<tN128, T, TG_SMEM>>>(x, W1, nullptr, pdinv, ph, pagg,
                                        N_NODES, 128, 64, 0);
    scatter_kernel<<<scatterBlocks, T>>>(ei, E, 128);
    combine_kernel<<<cdiv(N_NODES * 128, T), T>>>(b1, nullptr, pxa, 128);

    // ---- Layer 2
    tgemm_kernel<<<tN256, T, TG_SMEM>>>(pxa, Wr1, br1, nullptr, pres, nullptr,
                                        N_NODES, 256, 128, 0);
    tgemm_kernel<<<tN256, T, TG_SMEM>>>(pxa, W2, nullptr, pdinv, ph, pagg,
                                        N_NODES, 256, 128, 0);
    scatter_kernel<<<scatterBlocks, T>>>(ei, E, 256);
    combine_kernel<<<cdiv(N_NODES * 256, T), T>>>(b2, pres, pxb, 256);

    // ---- Layer 3
    tgemm_kernel<<<tN256, T, TG_SMEM>>>(pxb, Wr2, br2, nullptr, pres, nullptr,
                                        N_NODES, 256, 256, 0);
    tgemm_kernel<<<tN256, T, TG_SMEM>>>(pxb, W3, nullptr, pdinv, ph, pagg,
                                        N_NODES, 256, 256, 0);
    scatter_kernel<<<scatterBlocks, T>>>(ei, E, 256);
    combine_kernel<<<cdiv(N_NODES * 256, T), T>>>(b3, pres, pxa, 256);

    // ---- attention scores
    tgemm_kernel<<<tN256, T, TG_SMEM>>>(pxa, attn_W, nullptr, nullptr, ph, nullptr,
                                        N_NODES, 256, 256, 0);

    // ---- fingerprint / func-group branches
    fgemm_kernel<<<gB256f, T>>>(fpf, Wfp, bfp, nullptr, pfp, nullptr,
                                N_GRAPHS, 256, 2048, 1);
    sgemm_kernel<64,64,16><<<gB256s, T>>>(fgr, Wfg, bfg, nullptr, pfg, nullptr,
                                          N_GRAPHS, 256, 167, 1);

    // ---- softmax-attention mean pool + final projection
    pool_kernel<<<cdiv(N_NODES * 32, T), T>>>(batch);
    final_kernel<<<cdiv(N_GRAPHS * 32, T), T>>>(Wfc, bfc, out);
}

// round 12
// speedup vs baseline: 1.2241x; 1.2241x over previous
#include <cuda_runtime.h>
#include <cuda_bf16.h>
#include <cstdint>

#define N_NODES 50000
#define N_GRAPHS 1024
#define MAXC 256
#define EMAX 800000

// ---------------- static scratch (no allocation allowed) ----------------
__device__ float d_h  [N_NODES * MAXC];   // g = dinv * (X @ W)  (gather source)
__device__ float d_res[N_NODES * MAXC];   // residual branch
__device__ float d_xa [N_NODES * MAXC];   // x1 / x3
__device__ float d_xb [N_NODES * MAXC];   // x2
__device__ float d_dinv[N_NODES];
__device__ int   d_cntin [N_NODES];       // in-degree (int)
__device__ int   d_rowptr[N_NODES + 1];
__device__ int   d_cursor[N_NODES];
__device__ int   d_csrc  [EMAX];          // CSR-by-dst: src ids
__device__ float d_fp  [N_GRAPHS * MAXC];
__device__ float d_fg  [N_GRAPHS * MAXC];
__device__ float d_sums[N_GRAPHS * MAXC];
__device__ float d_cnt [N_GRAPHS];

// ---------------- init / CSR build ----------------
__global__ void zero_kernel() {
    int total = N_NODES + N_GRAPHS * MAXC + N_GRAPHS;
    for (int i = blockIdx.x * blockDim.x + threadIdx.x; i < total;
         i += gridDim.x * blockDim.x) {
        if (i < N_NODES) d_cntin[i] = 0;
        else if (i < N_NODES + N_GRAPHS * MAXC) d_sums[i - N_NODES] = 0.0f;
        else d_cnt[i - N_NODES - N_GRAPHS * MAXC] = 0.0f;
    }
}

__global__ void count_kernel(const int* __restrict__ ei, int E) {
    int e = blockIdx.x * blockDim.x + threadIdx.x;
    if (e < E) {
        unsigned d = (unsigned)ei[E + e];
        if (d < N_NODES) atomicAdd(&d_cntin[d], 1);
    }
}

// single-block exclusive scan over d_cntin -> d_rowptr / d_cursor
__global__ void scan_kernel() {
    __shared__ int ps[1024];
    int tid = threadIdx.x;
    const int CH = (N_NODES + 1023) / 1024;
    int base = tid * CH;
    int s = 0;
    for (int i = 0; i < CH; i++) {
        int idx = base + i;
        if (idx < N_NODES) s += d_cntin[idx];
    }
    ps[tid] = s;
    __syncthreads();
    if (tid == 0) {
        int run = 0;
        for (int i = 0; i < 1024; i++) { int t = ps[i]; ps[i] = run; run += t; }
        d_rowptr[N_NODES] = run;
    }
    __syncthreads();
    int o = ps[tid];
    for (int i = 0; i < CH; i++) {
        int idx = base + i;
        if (idx < N_NODES) {
            d_rowptr[idx] = o;
            d_cursor[idx] = o;
            o += d_cntin[idx];
        }
    }
}

__global__ void fill_kernel(const int* __restrict__ ei, int E) {
    int e = blockIdx.x * blockDim.x + threadIdx.x;
    if (e < E) {
        unsigned s = (unsigned)ei[e];
        unsigned d = (unsigned)ei[E + e];
        if (s < N_NODES && d < N_NODES) {
            int pos = atomicAdd(&d_cursor[d], 1);
            d_csrc[pos] = (int)s;
        }
    }
}

__global__ void dinv_kernel() {
    int i = blockIdx.x * blockDim.x + threadIdx.x;
    if (i < N_NODES) d_dinv[i] = rsqrtf((float)d_cntin[i] + 1.0f);
}

// ---------------- SIMT fgemm: 128x128x16, 8x8 microtile, double-buffered ---
// C = A@W; epilogue v = acc*rowscale[row] + bias[col]; relu opt.
__global__ __launch_bounds__(256, 1)
void fgemm_kernel(const float* __restrict__ A, const float* __restrict__ B,
                  const float* __restrict__ bias, const float* __restrict__ rowscale,
                  float* __restrict__ C,
                  int M, int N, int K, int do_relu)
{
    const int BM = 128, BN = 128, BK = 16;
    __shared__ float As[2][BK][BM + 4];
    __shared__ float Bs[2][BK][BN];
    int tid = threadIdx.x;
    int tx  = tid & 15;
    int ty  = tid >> 4;
    int row0 = blockIdx.y * BM;
    int col0 = blockIdx.x * BN;
    float acc[8][8];
    #pragma unroll
    for (int i = 0; i < 8; i++)
        #pragma unroll
        for (int j = 0; j < 8; j++) acc[i][j] = 0.0f;
    const int ntiles = K / BK;
    float4 pa[2], pb[2];
    auto gload = [&](int kt) {
        int k0 = kt * BK;
        #pragma unroll
        for (int l = 0; l < 2; l++) {
            int idx = tid + l * 256;
            int ar  = idx >> 2;
            int ac4 = idx & 3;
            int gr  = row0 + ar;
            pa[l] = (gr < M) ? *(const float4*)&A[(size_t)gr * K + k0 + ac4 * 4]
                             : make_float4(0.f, 0.f, 0.f, 0.f);
            int br  = idx >> 5;
            int bc4 = idx & 31;
            pb[l] = *(const float4*)&B[(size_t)(k0 + br) * N + col0 + bc4 * 4];
        }
    };
    auto sstore = [&](int buf) {
        #pragma unroll
        for (int l = 0; l < 2; l++) {
            int idx = tid + l * 256;
            int ar  = idx >> 2;
            int ac4 = idx & 3;
            As[buf][ac4 * 4 + 0][ar] = pa[l].x;
            As[buf][ac4 * 4 + 1][ar] = pa[l].y;
            As[buf][ac4 * 4 + 2][ar] = pa[l].z;
            As[buf][ac4 * 4 + 3][ar] = pa[l].w;
            int br  = idx >> 5;
            int bc4 = idx & 31;
            *(float4*)&Bs[buf][br][bc4 * 4] = pb[l];
        }
    };
    gload(0); sstore(0); __syncthreads();
    for (int kt = 0; kt < ntiles; kt++) {
        int cur = kt & 1;
        if (kt + 1 < ntiles) gload(kt + 1);
        #pragma unroll
        for (int kk = 0; kk < BK; kk++) {
            float a[8], b[8];
            *(float4*)&a[0] = *(const float4*)&As[cur][kk][ty * 8];
            *(float4*)&a[4] = *(const float4*)&As[cur][kk][ty * 8 + 4];
            *(float4*)&b[0] = *(const float4*)&Bs[cur][kk][tx * 8];
            *(float4*)&b[4] = *(const float4*)&Bs[cur][kk][tx * 8 + 4];
            #pragma unroll
            for (int i = 0; i < 8; i++)
                #pragma unroll
                for (int j = 0; j < 8; j++)
                    acc[i][j] = fmaf(a[i], b[j], acc[i][j]);
        }
        if (kt + 1 < ntiles) { sstore(cur ^ 1); __syncthreads(); }
    }
    float bvals[8];
    if (bias) {
        *(float4*)&bvals[0] = *(const float4*)&bias[col0 + tx * 8];
        *(float4*)&bvals[4] = *(const float4*)&bias[col0 + tx * 8 + 4];
    } else {
        #pragma unroll
        for (int j = 0; j < 8; j++) bvals[j] = 0.0f;
    }
    #pragma unroll
    for (int i = 0; i < 8; i++) {
        int gr = row0 + ty * 8 + i;
        if (gr >= M) continue;
        float rs = rowscale ? rowscale[gr] : 1.0f;
        float v[8];
        #pragma unroll
        for (int j = 0; j < 8; j++) {
            float t = acc[i][j] * rs + bvals[j];
            v[j] = do_relu ? fmaxf(t, 0.0f) : t;
        }
        size_t base = (size_t)gr * N + col0 + tx * 8;
        *(float4*)&C[base]     = *(float4*)&v[0];
        *(float4*)&C[base + 4] = *(float4*)&v[4];
    }
}

// ---------------- generic SGEMM for irregular shapes (K=167) ----------------
template<int BM, int BN, int BK>
__global__ __launch_bounds__(256)
void sgemm_kernel(const float* __restrict__ A, const float* __restrict__ W,
                  const float* __restrict__ bias,
                  float* __restrict__ C,
                  int M, int N, int K, int do_relu)
{
    __shared__ float As[BM][BK + 1];
    __shared__ float Bs[BK][BN + 1];
    const int TM = 4, TN = 4;
    int tid = threadIdx.x;
    int tx  = tid % (BN / TN);
    int ty  = tid / (BN / TN);
    int row0 = blockIdx.y * BM;
    int col0 = blockIdx.x * BN;
    float acc[TM][TN];
    #pragma unroll
    for (int i = 0; i < TM; i++)
        #pragma unroll
        for (int j = 0; j < TN; j++) acc[i][j] = 0.0f;
    for (int k0 = 0; k0 < K; k0 += BK) {
        for (int i = tid; i < BM * BK; i += 256) {
            int r = i / BK, c = i % BK;
            int gr = row0 + r, gc = k0 + c;
            As[r][c] = (gr < M && gc < K) ? A[(size_t)gr * K + gc] : 0.0f;
        }
        for (int i = tid; i < BK * BN; i += 256) {
            int r = i / BN, c = i % BN;
            int gr = k0 + r, gc = col0 + c;
            Bs[r][c] = (gr < K && gc < N) ? W[(size_t)gr * N + gc] : 0.0f;
        }
        __syncthreads();
        #pragma unroll
        for (int kk = 0; kk < BK; kk++) {
            float a[TM], b[TN];
            #pragma unroll
            for (int i = 0; i < TM; i++) a[i] = As[ty * TM + i][kk];
            #pragma unroll
            for (int j = 0; j < TN; j++) b[j] = Bs[kk][tx * TN + j];
            #pragma unroll
            for (int i = 0; i < TM; i++)
                #pragma unroll
                for (int j = 0; j < TN; j++) acc[i][j] += a[i] * b[j];
        }
        __syncthreads();
    }
    #pragma unroll
    for (int i = 0; i < TM; i++) {
        int gr = row0 + ty * TM + i;
        if (gr >= M) continue;
        #pragma unroll
        for (int j = 0; j < TN; j++) {
            int gc = col0 + tx * TN + j;
            if (gc >= N) continue;
            float v = acc[i][j];
            if (bias) v += bias[gc];
            if (do_relu) v = fmaxf(v, 0.0f);
            C[(size_t)gr * N + gc] = v;
        }
    }
}

// ---------------- CSR gather-aggregate + fused combine ----------------
// One warp per dst node: sum = g[dst] + sum_{src in CSR[dst]} g[src];
// out = relu(dinv[dst]*sum + bias (+res)). No atomics.
__global__ void gather_kernel(const float* __restrict__ bias,
                              const float* __restrict__ res,
                              float* __restrict__ out, int C) {
    int node = (blockIdx.x * blockDim.x + threadIdx.x) >> 5;
    int lane = threadIdx.x & 31;
    if (node >= N_NODES) return;
    int beg = d_rowptr[node];
    int end = d_rowptr[node + 1];
    const int Q = C >> 7;               // float4 per lane: 1 (C=128) or 2 (C=256)

    float4 acc[2];
    const float4* self = (const float4*)(d_h + (size_t)node * C);
    #pragma unroll
    for (int q = 0; q < 2; q++)
        if (q < Q) acc[q] = self[lane + 32 * q];

    int e = beg;
    for (; e + 2 <= end; e += 2) {
        int s0 = d_csrc[e];
        int s1 = d_csrc[e + 1];
        const float4* r0 = (const float4*)(d_h + (size_t)s0 * C);
        const float4* r1 = (const float4*)(d_h + (size_t)s1 * C);
        float4 v0[2], v1[2];
        #pragma unroll
        for (int q = 0; q < 2; q++)
            if (q < Q) { v0[q] = r0[lane + 32 * q]; v1[q] = r1[lane + 32 * q]; }
        #pragma unroll
        for (int q = 0; q < 2; q++)
            if (q < Q) {
                acc[q].x += v0[q].x + v1[q].x;
                acc[q].y += v0[q].y + v1[q].y;
                acc[q].z += v0[q].z + v1[q].z;
                acc[q].w += v0[q].w + v1[q].w;
            }
    }
    if (e < end) {
        int s0 = d_csrc[e];
        const float4* r0 = (const float4*)(d_h + (size_t)s0 * C);
        #pragma unroll
        for (int q = 0; q < 2; q++)
            if (q < Q) {
                float4 v = r0[lane + 32 * q];
                acc[q].x += v.x; acc[q].y += v.y;
                acc[q].z += v.z; acc[q].w += v.w;
            }
    }

    float di = d_dinv[node];
    #pragma unroll
    for (int q = 0; q < 2; q++) {
        if (q >= Q) break;
        int c = (lane + 32 * q) * 4;
        float4 bv = *(const float4*)&bias[c];
        float4 o;
        o.x = di * acc[q].x + bv.x;
        o.y = di * acc[q].y + bv.y;
        o.z = di * acc[q].z + bv.z;
        o.w = di * acc[q].w + bv.w;
        if (res) {
            float4 rv = *(const float4*)&res[(size_t)node * C + c];
            o.x += rv.x; o.y += rv.y; o.z += rv.z; o.w += rv.w;
        }
        o.x = fmaxf(o.x, 0.f); o.y = fmaxf(o.y, 0.f);
        o.z = fmaxf(o.z, 0.f); o.w = fmaxf(o.w, 0.f);
        *(float4*)&out[(size_t)node * C + c] = o;
    }
}

// ---------------- fused softmax-attention + mean-pool accumulate ------------
__global__ void pool_kernel(const int* __restrict__ batch) {
    int node = (blockIdx.x * blockDim.x + threadIdx.x) >> 5;
    int lane = threadIdx.x & 31;
    if (node >= N_NODES) return;
    const float* srow = d_h  + (size_t)node * 256;
    const float* xrow = d_xa + (size_t)node * 256;
    float vals[8];
    float m = -3.0e38f;
    #pragma unroll
    for (int j = 0; j < 8; j++) { vals[j] = srow[lane + 32 * j]; m = fmaxf(m, vals[j]); }
    #pragma unroll
    for (int off = 16; off; off >>= 1) m = fmaxf(m, __shfl_xor_sync(0xffffffffu, m, off));
    float ssum = 0.0f;
    #pragma unroll
    for (int j = 0; j < 8; j++) { vals[j] = __expf(vals[j] - m); ssum += vals[j]; }
    #pragma unroll
    for (int off = 16; off; off >>= 1) ssum += __shfl_xor_sync(0xffffffffu, ssum, off);
    float inv = 1.0f / ssum;
    unsigned b = (unsigned)batch[node];
    if (b >= N_GRAPHS) return;
    float* orow = d_sums + (size_t)b * 256;
    #pragma unroll
    for (int j = 0; j < 8; j++) {
        atomicAdd(orow + lane + 32 * j, vals[j] * inv * xrow[lane + 32 * j]);
    }
    if (lane == 0) atomicAdd(&d_cnt[b], 1.0f);
}

// ---------------- final: out = (pooled + fp + fg) @ Wfc + bfc ----------------
__global__ void final_kernel(const float* __restrict__ Wfc,
                             const float* __restrict__ bfc,
                             float* __restrict__ out) {
    int b    = (blockIdx.x * blockDim.x + threadIdx.x) >> 5;
    int lane = threadIdx.x & 31;
    if (b >= N_GRAPHS) return;
    float invc = 1.0f / fmaxf(d_cnt[b], 1.0f);
    float acc = 0.0f;
    #pragma unroll
    for (int j = lane; j < 256; j += 32) {
        float v = d_sums[b * 256 + j] * invc + d_fp[b * 256 + j] + d_fg[b * 256 + j];
        acc += v * Wfc[j];
    }
    #pragma unroll
    for (int off = 16; off; off >>= 1) acc += __shfl_xor_sync(0xffffffffu, acc, off);
    if (lane == 0) out[b] = acc + bfc[0];
}

// ---------------- launch ----------------
extern "C" void kernel_launch(void* const* d_in, const int* in_sizes, int n_in,
                              void* d_out, int out_size) {
    const float* x     = (const float*)d_in[0];
    const int*   ei    = (const int*)d_in[1];     // int32 (JAX x64 disabled)
    const int*   batch = (const int*)d_in[2];
    const float* fpf = (const float*)d_in[3];
    const float* fgr = (const float*)d_in[4];
    const float* W1  = (const float*)d_in[5],  *b1  = (const float*)d_in[6];
    const float* W2  = (const float*)d_in[7],  *b2  = (const float*)d_in[8];
    const float* W3  = (const float*)d_in[9],  *b3  = (const float*)d_in[10];
    const float* Wr1 = (const float*)d_in[11], *br1 = (const float*)d_in[12];
    const float* Wr2 = (const float*)d_in[13], *br2 = (const float*)d_in[14];
    const float* Wfp = (const float*)d_in[15], *bfp = (const float*)d_in[16];
    const float* Wfg = (const float*)d_in[17], *bfg = (const float*)d_in[18];
    const float* attn_W = (const float*)d_in[19];
    const float* Wfc = (const float*)d_in[20], *bfc = (const float*)d_in[21];
    float* out = (float*)d_out;
    int E = in_sizes[1] / 2;

    float *ph, *pres, *pxa, *pxb, *pdinv, *pfp, *pfg;
    cudaGetSymbolAddress((void**)&ph,   d_h);
    cudaGetSymbolAddress((void**)&pres, d_res);
    cudaGetSymbolAddress((void**)&pxa,  d_xa);
    cudaGetSymbolAddress((void**)&pxb,  d_xb);
    cudaGetSymbolAddress((void**)&pdinv, d_dinv);
    cudaGetSymbolAddress((void**)&pfp,  d_fp);
    cudaGetSymbolAddress((void**)&pfg,  d_fg);

    const int T = 256;
    auto cdiv = [](int a, int b) { return (a + b - 1) / b; };

    // ---- CSR build + dinv
    zero_kernel<<<cdiv(N_NODES + N_GRAPHS * MAXC + N_GRAPHS, T), T>>>();
    count_kernel<<<cdiv(E, T), T>>>(ei, E);
    scan_kernel<<<1, 1024>>>();
    dinv_kernel<<<cdiv(N_NODES, T), T>>>();
    fill_kernel<<<cdiv(E, T), T>>>(ei, E);

    dim3 gN128(1, cdiv(N_NODES, 128));
    dim3 gN256(2, cdiv(N_NODES, 128));
    dim3 gB256f(2, cdiv(N_GRAPHS, 128));
    dim3 gB256s(256 / 64, cdiv(N_GRAPHS, 64));
    int gatherBlocks = cdiv(N_NODES * 32, T);

    // ---- Layer 1: g1 = dinv*(x@W1) -> d_h; x1 = gather+combine -> d_xa
    fgemm_kernel<<<gN128, T>>>(x, W1, nullptr, pdinv, ph, N_NODES, 128, 64, 0);
    gather_kernel<<<gatherBlocks, T>>>(b1, nullptr, pxa, 128);

    // ---- Layer 2
    fgemm_kernel<<<gN256, T>>>(pxa, Wr1, br1, nullptr, pres, N_NODES, 256, 128, 0);
    fgemm_kernel<<<gN256, T>>>(pxa, W2, nullptr, pdinv, ph, N_NODES, 256, 128, 0);
    gather_kernel<<<gatherBlocks, T>>>(b2, pres, pxb, 256);

    // ---- Layer 3
    fgemm_kernel<<<gN256, T>>>(pxb, Wr2, br2, nullptr, pres, N_NODES, 256, 256, 0);
    fgemm_kernel<<<gN256, T>>>(pxb, W3, nullptr, pdinv, ph, N_NODES, 256, 256, 0);
    gather_kernel<<<gatherBlocks, T>>>(b3, pres, pxa, 256);

    // ---- attention scores: s = x3 @ attn_W -> d_h
    fgemm_kernel<<<gN256, T>>>(pxa, attn_W, nullptr, nullptr, ph, N_NODES, 256, 256, 0);

    // ---- fingerprint / func-group branches
    fgemm_kernel<<<gB256f, T>>>(fpf, Wfp, bfp, nullptr, pfp, N_GRAPHS, 256, 2048, 1);
    sgemm_kernel<64,64,16><<<gB256s, T>>>(fgr, Wfg, bfg, pfg, N_GRAPHS, 256, 167, 1);

    // ---- softmax-attention mean pool + final projection
    pool_kernel<<<cdiv(N_NODES * 32, T), T>>>(batch);
    final_kernel<<<cdiv(N_GRAPHS * 32, T), T>>>(Wfc, bfc, out);
}